// round 2
// baseline (speedup 1.0000x reference)
#include <cuda_runtime.h>
#include <math.h>

// Problem constants (shapes fixed by the dataset; asserted implicitly by sizing)
#define LAMBDA   1e-3f
#define KDIM     128      // k (spectral basis size) == BM
#define DDIM     256      // d (feature dim), multiple of BN
#define SPLIT    55       // split-K chunks per GEMM (8*SPLIT*2 = 440 CTAs ~ one wave @occ3)
#define SPLITMAX 64
#define BM       128
#define BN       64
#define BK       16

// Scratch (device globals only — no runtime allocation allowed)
__device__ float g_partial[2 * SPLITMAX * KDIM * DDIM];  // 16 MB split-K partials
__device__ float g_A[KDIM * DDIM];
__device__ float g_B[KDIM * DDIM];
__device__ float g_AAt[KDIM * KDIM];
__device__ float g_BAt[KDIM * KDIM];

// ---------------------------------------------------------------------------
// Kernel 1: split-K SGEMM.  P[z,s] (128 x d tile-slice) = E[z][:, k0:k1] @ F[z][k0:k1, :]
// E is [k, N] row-major, F is [N, d] row-major. CTA tile 128x64, thread tile 8x4.
// ---------------------------------------------------------------------------
__global__ __launch_bounds__(256, 3)
void gemm_splitk(const float* __restrict__ Ex, const float* __restrict__ Fx,
                 const float* __restrict__ Ey, const float* __restrict__ Fy,
                 int N, int d, int Kc, int kd)
{
    const int z = blockIdx.z;
    const float* __restrict__ E = z ? Ey : Ex;
    const float* __restrict__ F = z ? Fy : Fx;
    const int s     = blockIdx.y;
    const int nbase = blockIdx.x * BN;

    const int k0 = s * Kc;
    const int k1 = min(k0 + Kc, N);

    __shared__ float sE[BK][BM + 4];   // [kk][m], +4 pad (keeps float4 alignment, eases banks)
    __shared__ float sF[BK][BN];       // [kk][n]

    const int tid = threadIdx.x;
    const int tx  = tid & 15;          // 16 thread-cols * 4 = 64 N
    const int ty  = tid >> 4;          // 16 thread-rows * 8 = 128 M

    float acc[8][4];
    #pragma unroll
    for (int i = 0; i < 8; i++)
        #pragma unroll
        for (int j = 0; j < 4; j++) acc[i][j] = 0.f;

    const bool vecok = ((N & 3) == 0) && ((d & 3) == 0);  // Kc is a BK multiple => kt stays aligned

    int kt = k0;
    while (kt < k1) {
        if (vecok && (kt + BK) <= k1) {
            // ---- vectorized loads ----
            #pragma unroll
            for (int r = 0; r < 2; r++) {
                int lin = tid + r * 256;        // 0..511 -> 512 float4 = 128x16 floats
                int m   = lin >> 2;
                int q   = lin & 3;
                float4 v = *(const float4*)(E + m * N + kt + q * 4);
                sE[q * 4 + 0][m] = v.x;
                sE[q * 4 + 1][m] = v.y;
                sE[q * 4 + 2][m] = v.z;
                sE[q * 4 + 3][m] = v.w;
            }
            {
                int kk = tid >> 4;
                int n4 = tid & 15;
                float4 w = *(const float4*)(F + (kt + kk) * d + nbase + n4 * 4);
                sF[kk][n4 * 4 + 0] = w.x;
                sF[kk][n4 * 4 + 1] = w.y;
                sF[kk][n4 * 4 + 2] = w.z;
                sF[kk][n4 * 4 + 3] = w.w;
            }
        } else {
            // ---- scalar guarded (tail) loads ----
            for (int lin = tid; lin < BM * BK; lin += 256) {
                int m  = lin & 127;
                int kk = lin >> 7;
                int t  = kt + kk;
                sE[kk][m] = (t < k1) ? E[m * N + t] : 0.f;
            }
            for (int lin = tid; lin < BK * BN; lin += 256) {
                int n  = lin & 63;
                int kk = lin >> 6;
                int t  = kt + kk;
                sF[kk][n] = (t < k1) ? F[t * d + nbase + n] : 0.f;
            }
        }
        __syncthreads();

        #pragma unroll
        for (int kk = 0; kk < BK; kk++) {
            float4 a0 = *(const float4*)&sE[kk][ty * 8 + 0];
            float4 a1 = *(const float4*)&sE[kk][ty * 8 + 4];
            float4 b  = *(const float4*)&sF[kk][tx * 4];
            float a[8] = {a0.x, a0.y, a0.z, a0.w, a1.x, a1.y, a1.z, a1.w};
            float bb[4] = {b.x, b.y, b.z, b.w};
            #pragma unroll
            for (int i = 0; i < 8; i++)
                #pragma unroll
                for (int j = 0; j < 4; j++)
                    acc[i][j] = fmaf(a[i], bb[j], acc[i][j]);
        }
        __syncthreads();
        kt += BK;
    }

    // write split-K partial tile
    float* P = g_partial + (size_t)(z * SPLIT + s) * kd;
    #pragma unroll
    for (int i = 0; i < 8; i++) {
        int m = ty * 8 + i;
        float4 v = make_float4(acc[i][0], acc[i][1], acc[i][2], acc[i][3]);
        *(float4*)(P + m * d + nbase + tx * 4) = v;
    }
}

// ---------------------------------------------------------------------------
// Kernel 2: deterministic split-K reduction  ->  g_A, g_B  ([k, d])
// ---------------------------------------------------------------------------
__global__ void reduce_partials(int kd)
{
    int idx = blockIdx.x * blockDim.x + threadIdx.x;
    if (idx >= 2 * kd) return;
    int z = idx / kd;
    int e = idx - z * kd;
    const float* P = g_partial + (size_t)z * SPLIT * kd;
    float sum = 0.f;
    #pragma unroll 4
    for (int s = 0; s < SPLIT; s++) sum += P[(size_t)s * kd + e];
    (z ? g_B : g_A)[e] = sum;
}

// ---------------------------------------------------------------------------
// Kernel 3: Gram matrices. AAt[i,j] = A_i . A_j ;  BAt[i,j] = B_i . A_j
// ---------------------------------------------------------------------------
__global__ __launch_bounds__(KDIM)
void gram_kernel(int k, int d)
{
    __shared__ float row[DDIM];
    const int i = blockIdx.x;
    const int z = blockIdx.y;
    const int j = threadIdx.x;
    const float* src = z ? g_B : g_A;
    for (int t = j; t < d; t += KDIM) row[t] = src[i * d + t];
    __syncthreads();
    const float* aj = g_A + j * d;
    float sum = 0.f;
    #pragma unroll 8
    for (int t = 0; t < d; t++) sum = fmaf(row[t], aj[t], sum);
    (z ? g_BAt : g_AAt)[i * k + j] = sum;
}

// ---------------------------------------------------------------------------
// Kernel 4: one CTA per output row i.
//   M_i = AAt + lambda * diag((evals_x[:] - evals_y[i])^2)   (SPD)
//   Solve M_i x = BAt[i,:] via packed-lower Cholesky + fwd/bwd substitution.
// ---------------------------------------------------------------------------
__global__ __launch_bounds__(KDIM)
void solve_kernel(const float* __restrict__ evx, const float* __restrict__ evy,
                  float* __restrict__ out, int k)
{
    __shared__ float P[KDIM * (KDIM + 1) / 2];  // packed lower triangle, 33 KB
    __shared__ float yv[KDIM];

    const int i = blockIdx.x;
    const int t = threadIdx.x;
    const int trit = t * (t + 1) / 2;

    // load lower triangle of AAt (symmetric), coalesced per row
    for (int r = 0; r < k; r++)
        if (t <= r) P[r * (r + 1) / 2 + t] = g_AAt[r * k + t];

    // diagonal regularizer (thread t loaded its own diagonal element -> no race)
    float ev = evx[t] - evy[i];
    P[trit + t] += LAMBDA * ev * ev;
    yv[t] = g_BAt[i * k + t];
    __syncthreads();

    // Cholesky (left-looking column updates, row-per-thread trailing update)
    for (int j = 0; j < k; j++) {
        if (t == j) P[trit + j] = sqrtf(P[trit + j]);
        __syncthreads();
        float Ljj = P[j * (j + 1) / 2 + j];
        float Ltj = 0.f;
        if (t > j) {
            Ltj = P[trit + j] / Ljj;
            P[trit + j] = Ltj;
        }
        __syncthreads();
        if (t > j) {
            int idx_c = (j + 1) * (j + 2) / 2 + j;  // tri(c)+j, c = j+1
            for (int c = j + 1; c <= t; c++) {
                P[trit + c] -= Ltj * P[idx_c];      // broadcast read of column j
                idx_c += (c + 1);
            }
        }
        __syncthreads();
    }

    // forward substitution: L y = b
    for (int j = 0; j < k; j++) {
        if (t == j) yv[j] /= P[trit + j];
        __syncthreads();
        float yj = yv[j];
        if (t > j) yv[t] -= P[trit + j] * yj;
        __syncthreads();
    }
    // backward substitution: L^T x = y
    for (int j = k - 1; j >= 0; j--) {
        if (t == j) yv[j] /= P[trit + j];
        __syncthreads();
        float yj = yv[j];
        if (t < j) yv[t] -= P[j * (j + 1) / 2 + t] * yj;
        __syncthreads();
    }
    out[i * k + t] = yv[t];
}

// ---------------------------------------------------------------------------
// Launch. Inputs (metadata order): feat_x, feat_y, evals_x, evals_y,
//                                  evecs_trans_x, evecs_trans_y. Output: C [k,k] fp32.
// ---------------------------------------------------------------------------
extern "C" void kernel_launch(void* const* d_in, const int* in_sizes, int n_in,
                              void* d_out, int out_size)
{
    const float* feat_x = (const float*)d_in[0];
    const float* feat_y = (const float*)d_in[1];
    const float* evals_x = (const float*)d_in[2];
    const float* evals_y = (const float*)d_in[3];
    const float* Ex = (const float*)d_in[4];
    const float* Ey = (const float*)d_in[5];

    const int  k  = in_sizes[2];                 // 128
    const long N  = (long)in_sizes[4] / k;       // 200000
    const int  d  = (int)((long)in_sizes[0] / N);// 256
    const int  kd = k * d;

    // split-K chunk, rounded up to a BK multiple so the vector path stays aligned
    int Kc = (int)((N + SPLIT - 1) / SPLIT);
    Kc = ((Kc + BK - 1) / BK) * BK;

    dim3 ggrid(d / BN, SPLIT, 2);
    gemm_splitk<<<ggrid, 256>>>(Ex, feat_x, Ey, feat_y, (int)N, d, Kc, kd);

    reduce_partials<<<(2 * kd + 255) / 256, 256>>>(kd);

    gram_kernel<<<dim3(k, 2), KDIM>>>(k, d);

    solve_kernel<<<k, KDIM>>>(evals_x, evals_y, (float*)d_out, k);
}

// round 3
// speedup vs baseline: 1.1834x; 1.1834x over previous
#include <cuda_runtime.h>
#include <math.h>

// Problem constants (shapes fixed by the dataset)
#define LAMBDA   1e-3f
#define KDIM     128      // k (spectral basis size) == BM
#define DDIM     256      // d (feature dim), multiple of BN
#define SPLIT    55       // split-K chunks per GEMM
#define SPLITMAX 64
#define BM       128
#define BN       64
#define BK       16
#define NB       16       // Cholesky block size

// Scratch (device globals only — no runtime allocation allowed)
__device__ float g_partial[2 * SPLITMAX * KDIM * DDIM];  // 16 MB split-K partials
__device__ float g_A[KDIM * DDIM];
__device__ float g_B[KDIM * DDIM];
__device__ float g_AAt[KDIM * KDIM];
__device__ float g_BAt[KDIM * KDIM];

// ---------------------------------------------------------------------------
// Kernel 1: split-K SGEMM.  P[z,s] (128 x d tile-slice) = E[z][:, k0:k1] @ F[z][k0:k1, :]
// ---------------------------------------------------------------------------
__global__ __launch_bounds__(256, 3)
void gemm_splitk(const float* __restrict__ Ex, const float* __restrict__ Fx,
                 const float* __restrict__ Ey, const float* __restrict__ Fy,
                 int N, int d, int Kc, int kd)
{
    const int z = blockIdx.z;
    const float* __restrict__ E = z ? Ey : Ex;
    const float* __restrict__ F = z ? Fy : Fx;
    const int s     = blockIdx.y;
    const int nbase = blockIdx.x * BN;

    const int k0 = s * Kc;
    const int k1 = min(k0 + Kc, N);

    __shared__ float sE[BK][BM + 4];
    __shared__ float sF[BK][BN];

    const int tid = threadIdx.x;
    const int tx  = tid & 15;
    const int ty  = tid >> 4;

    float acc[8][4];
    #pragma unroll
    for (int i = 0; i < 8; i++)
        #pragma unroll
        for (int j = 0; j < 4; j++) acc[i][j] = 0.f;

    const bool vecok = ((N & 3) == 0) && ((d & 3) == 0);

    int kt = k0;
    while (kt < k1) {
        if (vecok && (kt + BK) <= k1) {
            #pragma unroll
            for (int r = 0; r < 2; r++) {
                int lin = tid + r * 256;
                int m   = lin >> 2;
                int q   = lin & 3;
                float4 v = *(const float4*)(E + m * N + kt + q * 4);
                sE[q * 4 + 0][m] = v.x;
                sE[q * 4 + 1][m] = v.y;
                sE[q * 4 + 2][m] = v.z;
                sE[q * 4 + 3][m] = v.w;
            }
            {
                int kk = tid >> 4;
                int n4 = tid & 15;
                float4 w = *(const float4*)(F + (kt + kk) * d + nbase + n4 * 4);
                sF[kk][n4 * 4 + 0] = w.x;
                sF[kk][n4 * 4 + 1] = w.y;
                sF[kk][n4 * 4 + 2] = w.z;
                sF[kk][n4 * 4 + 3] = w.w;
            }
        } else {
            for (int lin = tid; lin < BM * BK; lin += 256) {
                int m  = lin & 127;
                int kk = lin >> 7;
                int t  = kt + kk;
                sE[kk][m] = (t < k1) ? E[m * N + t] : 0.f;
            }
            for (int lin = tid; lin < BK * BN; lin += 256) {
                int n  = lin & 63;
                int kk = lin >> 6;
                int t  = kt + kk;
                sF[kk][n] = (t < k1) ? F[t * d + nbase + n] : 0.f;
            }
        }
        __syncthreads();

        #pragma unroll
        for (int kk = 0; kk < BK; kk++) {
            float4 a0 = *(const float4*)&sE[kk][ty * 8 + 0];
            float4 a1 = *(const float4*)&sE[kk][ty * 8 + 4];
            float4 b  = *(const float4*)&sF[kk][tx * 4];
            float a[8] = {a0.x, a0.y, a0.z, a0.w, a1.x, a1.y, a1.z, a1.w};
            float bb[4] = {b.x, b.y, b.z, b.w};
            #pragma unroll
            for (int i = 0; i < 8; i++)
                #pragma unroll
                for (int j = 0; j < 4; j++)
                    acc[i][j] = fmaf(a[i], bb[j], acc[i][j]);
        }
        __syncthreads();
        kt += BK;
    }

    float* P = g_partial + (size_t)(z * SPLIT + s) * kd;
    #pragma unroll
    for (int i = 0; i < 8; i++) {
        int m = ty * 8 + i;
        float4 v = make_float4(acc[i][0], acc[i][1], acc[i][2], acc[i][3]);
        *(float4*)(P + m * d + nbase + tx * 4) = v;
    }
}

// ---------------------------------------------------------------------------
// Kernel 2: deterministic split-K reduction  ->  g_A, g_B  ([k, d])
// ---------------------------------------------------------------------------
__global__ void reduce_partials(int kd)
{
    int idx = blockIdx.x * blockDim.x + threadIdx.x;
    if (idx >= 2 * kd) return;
    int z = idx / kd;
    int e = idx - z * kd;
    const float* P = g_partial + (size_t)z * SPLIT * kd;
    float sum = 0.f;
    #pragma unroll 4
    for (int s = 0; s < SPLIT; s++) sum += P[(size_t)s * kd + e];
    (z ? g_B : g_A)[e] = sum;
}

// ---------------------------------------------------------------------------
// Kernel 3: Gram matrices. AAt[i,j] = A_i . A_j ;  BAt[i,j] = B_i . A_j
// ---------------------------------------------------------------------------
__global__ __launch_bounds__(KDIM)
void gram_kernel(int k, int d)
{
    __shared__ float row[DDIM];
    const int i = blockIdx.x;
    const int z = blockIdx.y;
    const int j = threadIdx.x;
    const float* src = z ? g_B : g_A;
    for (int t = j; t < d; t += KDIM) row[t] = src[i * d + t];
    __syncthreads();
    const float* aj = g_A + j * d;
    float sum = 0.f;
    #pragma unroll 8
    for (int t = 0; t < d; t++) sum = fmaf(row[t], aj[t], sum);
    (z ? g_BAt : g_AAt)[i * k + j] = sum;
}

// ---------------------------------------------------------------------------
// Kernel 4 (REWRITTEN): one CTA per output row i, 512 threads.
//   Blocked (NB=16) right-looking Cholesky on packed lower triangle:
//     - 16x16 diagonal block factored inside one warp via shuffles
//     - panel solve: thread-per-row, row panel held in registers
//     - SYRK trailing update: register panel + 4-way column striping
//   Then blocked forward/backward substitution.
// ---------------------------------------------------------------------------
__global__ __launch_bounds__(512, 1)
void solve_kernel(const float* __restrict__ evx, const float* __restrict__ evy,
                  float* __restrict__ out)
{
    __shared__ float P[KDIM * (KDIM + 1) / 2];   // packed lower triangle, 33 KB
    __shared__ float colb[NB][KDIM];             // current panel, transposed (8 KB)
    __shared__ float yv[KDIM];
    __shared__ float invDs[NB];

    const int i   = blockIdx.x;
    const int tid = threadIdx.x;
    const int t   = tid & 127;          // row id for striped phases
    const int q   = tid >> 7;           // 0..3 column stripe
    const int trit = t * (t + 1) / 2;

    // ---- load lower triangle of AAt (4 rows per pass, coalesced) ----
    for (int r0 = 0; r0 < KDIM; r0 += 4) {
        int r = r0 + q;
        int c = t;
        if (c <= r) P[r * (r + 1) / 2 + c] = g_AAt[r * KDIM + c];
    }
    if (tid < KDIM) yv[tid] = g_BAt[i * KDIM + tid];
    __syncthreads();

    // ---- diagonal regularizer ----
    if (tid < KDIM) {
        float ev = evx[tid] - evy[i];
        P[trit + tid] += LAMBDA * ev * ev;
    }
    __syncthreads();

    // ================= blocked Cholesky =================
    for (int b = 0; b < KDIM / NB; b++) {
        const int j0  = b * NB;
        const int rlo = j0 + NB;

        // ---- DIAG: warp 0 factors the 16x16 block with shuffles ----
        if (tid < 32) {
            int l = tid & 15;
            int row = j0 + l;
            int trow = row * (row + 1) / 2;
            float dreg[NB];
            #pragma unroll
            for (int c = 0; c < NB; c++)
                dreg[c] = (c <= l) ? P[trow + j0 + c] : 0.f;

            #pragma unroll
            for (int c = 0; c < NB; c++) {
                float dc = __shfl_sync(0xffffffffu, dreg[c], c);
                float s  = sqrtf(dc);
                if (l == c)      dreg[c] = s;
                else if (l > c)  dreg[c] /= s;
                #pragma unroll
                for (int m = c + 1; m < NB; m++) {
                    float Lmc = __shfl_sync(0xffffffffu, dreg[c], m);
                    if (l >= m) dreg[m] -= dreg[c] * Lmc;
                }
            }
            if (tid < 16) {
                #pragma unroll
                for (int c = 0; c < NB; c++)
                    if (c <= l) P[trow + j0 + c] = dreg[c];
                invDs[l] = 1.0f / dreg[l];
            }
        }
        __syncthreads();

        if (rlo >= KDIM) break;   // last block has no trailing part

        // ---- PANEL: rows rlo..127, one thread per row, row panel in regs ----
        {
            int r = rlo + tid;
            if (r < KDIM) {
                int trr = r * (r + 1) / 2;
                float a[NB];
                #pragma unroll
                for (int j = 0; j < NB; j++) a[j] = P[trr + j0 + j];
                #pragma unroll
                for (int j = 0; j < NB; j++) {
                    float v = a[j];
                    int trj = (j0 + j) * (j0 + j + 1) / 2;
                    #pragma unroll
                    for (int c = 0; c < j; c++)
                        v -= a[c] * P[trj + j0 + c];
                    a[j] = v * invDs[j];
                }
                #pragma unroll
                for (int j = 0; j < NB; j++) {
                    P[trr + j0 + j] = a[j];
                    colb[j][r] = a[j];
                }
            }
        }
        __syncthreads();

        // ---- SYRK: trailing update, register panel, 4-way c striping ----
        if (t >= rlo) {
            float ar[NB];
            #pragma unroll
            for (int j = 0; j < NB; j++) ar[j] = colb[j][t];
            for (int c = rlo + q; c <= t; c += 4) {
                float acc = P[trit + c];
                #pragma unroll
                for (int j = 0; j < NB; j++) acc -= ar[j] * colb[j][c];
                P[trit + c] = acc;
            }
        }
        __syncthreads();
    }

    // ================= forward substitution: L y = b =================
    for (int b = 0; b < KDIM / NB; b++) {
        const int j0 = b * NB;
        if (tid < 32) {
            int l = tid & 15;
            int row = j0 + l;
            int trow = row * (row + 1) / 2;
            float yl = yv[row];
            #pragma unroll
            for (int c = 0; c < NB; c++) {
                int rc = j0 + c;
                int trc = rc * (rc + 1) / 2;
                float Dcc = P[trc + rc];
                float t2 = yl / Dcc;
                yl = (l == c) ? t2 : yl;
                float yc = __shfl_sync(0xffffffffu, yl, c);
                if (l > c) yl -= P[trow + rc] * yc;
            }
            if (tid < 16) yv[row] = yl;
        }
        __syncthreads();
        {
            int r = j0 + NB + tid;
            if (r < KDIM) {
                int trr = r * (r + 1) / 2;
                float acc = yv[r];
                #pragma unroll
                for (int c = 0; c < NB; c++)
                    acc -= P[trr + j0 + c] * yv[j0 + c];
                yv[r] = acc;
            }
        }
        __syncthreads();
    }

    // ================= backward substitution: L^T x = y =================
    for (int b = KDIM / NB - 1; b >= 0; b--) {
        const int j0 = b * NB;
        if (tid < 32) {
            int l = tid & 15;
            int row = j0 + l;
            float xl = yv[row];
            #pragma unroll
            for (int c = NB - 1; c >= 0; c--) {
                int rc = j0 + c;
                int trc = rc * (rc + 1) / 2;
                float Dcc = P[trc + rc];
                float t2 = xl / Dcc;
                xl = (l == c) ? t2 : xl;
                float xc = __shfl_sync(0xffffffffu, xl, c);
                if (l < c) xl -= P[trc + row] * xc;
            }
            if (tid < 16) yv[row] = xl;
        }
        __syncthreads();
        {
            int r = tid;
            if (r < j0) {
                float acc = yv[r];
                #pragma unroll
                for (int c = 0; c < NB; c++) {
                    int rc = j0 + c;
                    acc -= P[rc * (rc + 1) / 2 + r] * yv[rc];
                }
                yv[r] = acc;
            }
        }
        __syncthreads();
    }

    if (tid < KDIM) out[i * KDIM + tid] = yv[tid];
}

// ---------------------------------------------------------------------------
// Launch. Inputs (metadata order): feat_x, feat_y, evals_x, evals_y,
//                                  evecs_trans_x, evecs_trans_y. Output: C [k,k] fp32.
// ---------------------------------------------------------------------------
extern "C" void kernel_launch(void* const* d_in, const int* in_sizes, int n_in,
                              void* d_out, int out_size)
{
    const float* feat_x = (const float*)d_in[0];
    const float* feat_y = (const float*)d_in[1];
    const float* evals_x = (const float*)d_in[2];
    const float* evals_y = (const float*)d_in[3];
    const float* Ex = (const float*)d_in[4];
    const float* Ey = (const float*)d_in[5];

    const int  k  = in_sizes[2];                 // 128
    const long N  = (long)in_sizes[4] / k;       // 200000
    const int  d  = (int)((long)in_sizes[0] / N);// 256
    const int  kd = k * d;

    int Kc = (int)((N + SPLIT - 1) / SPLIT);
    Kc = ((Kc + BK - 1) / BK) * BK;

    dim3 ggrid(d / BN, SPLIT, 2);
    gemm_splitk<<<ggrid, 256>>>(Ex, feat_x, Ey, feat_y, (int)N, d, Kc, kd);

    reduce_partials<<<(2 * kd + 255) / 256, 256>>>(kd);

    gram_kernel<<<dim3(k, 2), KDIM>>>(k, d);

    solve_kernel<<<k, 512>>>(evals_x, evals_y, (float*)d_out);
}

// round 5
// speedup vs baseline: 1.2977x; 1.0966x over previous
#include <cuda_runtime.h>
#include <cstdint>
#include <math.h>

// Problem constants (dataset-fixed shapes)
#define LAMBDA   1e-3f
#define KDIM     128      // k
#define DDIM     256      // d
#define NSPLIT   37       // split-K chunks (2 ntiles * 37 * 2 tensors = 148 CTAs = 1 wave)
#define KB       32       // K per mainloop stage
#define NB       16       // Cholesky block size

// Scratch (device globals only)
__device__ float g_partial[2 * NSPLIT * KDIM * DDIM];   // ~9.7 MB split-K partials
__device__ float g_A[KDIM * DDIM];
__device__ float g_B[KDIM * DDIM];
__device__ float g_AAt[KDIM * KDIM];
__device__ float g_BAt[KDIM * KDIM];

// ---------------------------------------------------------------------------
// helpers
// ---------------------------------------------------------------------------
__device__ __forceinline__ uint32_t smem_u32(const void* p) {
    uint32_t a;
    asm("{ .reg .u64 t; cvta.to.shared.u64 t, %1; cvt.u32.u64 %0, t; }" : "=r"(a) : "l"(p));
    return a;
}
__device__ __forceinline__ float f2tf32(float x) {
    uint32_t r;
    asm("cvt.rna.tf32.f32 %0, %1;" : "=r"(r) : "f"(x));
    return __uint_as_float(r);
}
__device__ __forceinline__ void sts64(uint32_t a, float x, float y) {
    asm volatile("st.shared.v2.f32 [%0], {%1,%2};" :: "r"(a), "f"(x), "f"(y) : "memory");
}
__device__ __forceinline__ void sts128(uint32_t a, float x, float y, float z, float w) {
    asm volatile("st.shared.v4.f32 [%0], {%1,%2,%3,%4};" :: "r"(a), "f"(x), "f"(y), "f"(z), "f"(w) : "memory");
}
__device__ __forceinline__ uint4 lds128(uint32_t a) {
    uint4 v;
    asm volatile("ld.shared.v4.b32 {%0,%1,%2,%3}, [%4];"
                 : "=r"(v.x), "=r"(v.y), "=r"(v.z), "=r"(v.w) : "r"(a));
    return v;
}
__device__ __forceinline__ uint32_t lds32(uint32_t a) {
    uint32_t v;
    asm volatile("ld.shared.b32 %0, [%1];" : "=r"(v) : "r"(a));
    return v;
}
// tf32 mma: D(16x8) += A(16x8) * B(8x8);  base-PTX, sm_80+
__device__ __forceinline__ void mma_tf32(float* c,
                                         uint32_t a0, uint32_t a1, uint32_t a2, uint32_t a3,
                                         uint32_t b0, uint32_t b1) {
    asm volatile(
        "mma.sync.aligned.m16n8k8.row.col.f32.tf32.tf32.f32 "
        "{%0,%1,%2,%3}, {%4,%5,%6,%7}, {%8,%9}, {%0,%1,%2,%3};"
        : "+f"(c[0]), "+f"(c[1]), "+f"(c[2]), "+f"(c[3])
        : "r"(a0), "r"(a1), "r"(a2), "r"(a3), "r"(b0), "r"(b1));
}

// ---------------------------------------------------------------------------
// SMEM layout (dynamic):
//   per stage: sA 128 rows x 320B (chunk f(g,kk)=((g+kk)&3)*16+kk*64, +half*8)
//              sBh [g4][kk4][half2][n128] fp32 (hi plane, 16KB)
//              sBl same (lo plane, 16KB)
// ---------------------------------------------------------------------------
#define A_STRIDE   320
#define A_BYTES    (128 * A_STRIDE)          // 40960
#define BPLANE     16384
#define STAGE      (A_BYTES + 2 * BPLANE)    // 73728
#define SMEM_GEMM  (2 * STAGE)               // 147456

// ---------------------------------------------------------------------------
// Kernel 1: 3xTF32 mma.sync split-K GEMM.
//   partial[z,s][128, ntile*128 .. +128] = E[z][:, k0:k1] @ F[z][k0:k1, ntile tile]
// ---------------------------------------------------------------------------
__global__ __launch_bounds__(256, 1)
void gemm_mma(const float* __restrict__ Ex, const float* __restrict__ Fx,
              const float* __restrict__ Ey, const float* __restrict__ Fy,
              int N, int d, int Kc, int kd)
{
    extern __shared__ char smem[];
    const uint32_t sbase = smem_u32(smem);

    const int ntile = blockIdx.x;          // 0,1 -> which 128 of d=256
    const int s     = blockIdx.y;          // split-K chunk
    const int z     = blockIdx.z;          // tensor select
    const float* __restrict__ E = z ? Ey : Ex;
    const float* __restrict__ F = z ? Fy : Fx;

    const int k0 = s * Kc;
    const int k1 = min(k0 + Kc, N);
    const int ntiles = (k1 - k0 + KB - 1) / KB;

    const int tid  = threadIdx.x;
    const int lane = tid & 31;
    const int wid  = tid >> 5;
    const int warpM = wid & 3;             // 4 warps over M -> 32 rows each
    const int warpN = wid >> 2;            // 2 warps over N -> 64 cols each

    float acc[2][8][4];
    #pragma unroll
    for (int a = 0; a < 2; a++)
        #pragma unroll
        for (int b = 0; b < 8; b++)
            #pragma unroll
            for (int c = 0; c < 4; c++) acc[a][b][c] = 0.f;

    float4 ra[4], rb[4];

    // ---- prologue: load tile 0 into registers ----
    {
        const int kt = k0;
        const bool full = (kt + KB) <= k1;
        #pragma unroll
        for (int r = 0; r < 4; r++) {
            int f = tid + r * 256;
            int m = f >> 3, kq = f & 7;
            if (full) {
                ra[r] = *(const float4*)(E + (size_t)m * N + kt + kq * 4);
            } else {
                float tv[4];
                #pragma unroll
                for (int jj = 0; jj < 4; jj++) {
                    int kk2 = kt + kq * 4 + jj;
                    tv[jj] = (kk2 < k1) ? E[(size_t)m * N + kk2] : 0.f;
                }
                ra[r] = make_float4(tv[0], tv[1], tv[2], tv[3]);
            }
        }
        #pragma unroll
        for (int r = 0; r < 4; r++) {
            int f = tid + r * 256;
            int krow = f >> 5, nq = f & 31;
            int kk2 = kt + krow;
            if (kk2 < k1)
                rb[r] = *(const float4*)(F + (size_t)kk2 * d + ntile * 128 + nq * 4);
            else
                rb[r] = make_float4(0.f, 0.f, 0.f, 0.f);
        }
    }

    for (int t = 0; t < ntiles; t++) {
        const int buf = t & 1;
        const uint32_t sA  = sbase + buf * STAGE;
        const uint32_t sBh = sA + A_BYTES;
        const uint32_t sBl = sBh + BPLANE;

        // ---- STS: split hi/lo and store tile t ----
        #pragma unroll
        for (int r = 0; r < 4; r++) {
            int f = tid + r * 256;
            int m = f >> 3, kq = f & 7;
            float v[4] = {ra[r].x, ra[r].y, ra[r].z, ra[r].w};
            #pragma unroll
            for (int jj = 0; jj < 4; jj++) {
                int k = kq * 4 + jj;
                int g = k >> 3, kk = k & 3, hf = (k >> 2) & 1;
                float hi = f2tf32(v[jj]);
                float lo = f2tf32(v[jj] - hi);
                uint32_t off = (uint32_t)(m * A_STRIDE + (((g + kk) & 3) << 4) + (kk << 6) + (hf << 3));
                sts64(sA + off, hi, lo);
            }
        }
        #pragma unroll
        for (int r = 0; r < 4; r++) {
            int f = tid + r * 256;
            int krow = f >> 5, nq = f & 31;
            int g = krow >> 3, kk = krow & 3, hf = (krow >> 2) & 1;
            float v[4] = {rb[r].x, rb[r].y, rb[r].z, rb[r].w};
            float hi[4], lo[4];
            #pragma unroll
            for (int jj = 0; jj < 4; jj++) {
                hi[jj] = f2tf32(v[jj]);
                lo[jj] = f2tf32(v[jj] - hi[jj]);
            }
            uint32_t off = (uint32_t)((((g * 4 + kk) * 2 + hf) << 9) + (nq << 4));
            sts128(sBh + off, hi[0], hi[1], hi[2], hi[3]);
            sts128(sBl + off, lo[0], lo[1], lo[2], lo[3]);
        }
        __syncthreads();

        // ---- prefetch tile t+1 into registers ----
        if (t + 1 < ntiles) {
            const int kt = k0 + (t + 1) * KB;
            const bool full = (kt + KB) <= k1;
            #pragma unroll
            for (int r = 0; r < 4; r++) {
                int f = tid + r * 256;
                int m = f >> 3, kq = f & 7;
                if (full) {
                    ra[r] = *(const float4*)(E + (size_t)m * N + kt + kq * 4);
                } else {
                    float tv[4];
                    #pragma unroll
                    for (int jj = 0; jj < 4; jj++) {
                        int kk2 = kt + kq * 4 + jj;
                        tv[jj] = (kk2 < k1) ? E[(size_t)m * N + kk2] : 0.f;
                    }
                    ra[r] = make_float4(tv[0], tv[1], tv[2], tv[3]);
                }
            }
            #pragma unroll
            for (int r = 0; r < 4; r++) {
                int f = tid + r * 256;
                int krow = f >> 5, nq = f & 31;
                int kk2 = kt + krow;
                if (kk2 < k1)
                    rb[r] = *(const float4*)(F + (size_t)kk2 * d + ntile * 128 + nq * 4);
                else
                    rb[r] = make_float4(0.f, 0.f, 0.f, 0.f);
            }
        }

        // ---- compute tile t ----
        const int kk = lane & 3;
        const int rsub = lane >> 2;
        #pragma unroll
        for (int g = 0; g < 4; g++) {
            const uint32_t fA = (uint32_t)((((g + kk) & 3) << 4) + (kk << 6));
            const int rbase = warpM * 32 + rsub;
            uint4 A0 = lds128(sA + (uint32_t)((rbase +  0) * A_STRIDE) + fA);
            uint4 A1 = lds128(sA + (uint32_t)((rbase +  8) * A_STRIDE) + fA);
            uint4 A2 = lds128(sA + (uint32_t)((rbase + 16) * A_STRIDE) + fA);
            uint4 A3 = lds128(sA + (uint32_t)((rbase + 24) * A_STRIDE) + fA);
            const uint32_t bchunk = (uint32_t)((g * 4 + kk) * 2);
            #pragma unroll
            for (int j = 0; j < 8; j++) {
                const int n = warpN * 64 + j * 8 + rsub;
                uint32_t b0h = lds32(sBh + ((bchunk + 0) << 9) + (n << 2));
                uint32_t b1h = lds32(sBh + ((bchunk + 1) << 9) + (n << 2));
                uint32_t b0l = lds32(sBl + ((bchunk + 0) << 9) + (n << 2));
                uint32_t b1l = lds32(sBl + ((bchunk + 1) << 9) + (n << 2));
                // mt = 0
                mma_tf32(acc[0][j], A0.x, A1.x, A0.z, A1.z, b0h, b1h);  // hh
                mma_tf32(acc[0][j], A0.y, A1.y, A0.w, A1.w, b0h, b1h);  // lh
                mma_tf32(acc[0][j], A0.x, A1.x, A0.z, A1.z, b0l, b1l);  // hl
                // mt = 1
                mma_tf32(acc[1][j], A2.x, A3.x, A2.z, A3.z, b0h, b1h);
                mma_tf32(acc[1][j], A2.y, A3.y, A2.w, A3.w, b0h, b1h);
                mma_tf32(acc[1][j], A2.x, A3.x, A2.z, A3.z, b0l, b1l);
            }
        }
        __syncthreads();
    }

    // ---- epilogue: write split-K partial tile ----
    float* P = g_partial + (size_t)(z * NSPLIT + s) * kd;
    const int rsub = lane >> 2;
    const int csub = (lane & 3) * 2;
    #pragma unroll
    for (int mt = 0; mt < 2; mt++) {
        #pragma unroll
        for (int j = 0; j < 8; j++) {
            int row = warpM * 32 + mt * 16 + rsub;
            int col = ntile * 128 + warpN * 64 + j * 8 + csub;
            float2 v0 = make_float2(acc[mt][j][0], acc[mt][j][1]);
            float2 v1 = make_float2(acc[mt][j][2], acc[mt][j][3]);
            *(float2*)(P + (size_t)row * DDIM + col)       = v0;
            *(float2*)(P + (size_t)(row + 8) * DDIM + col) = v1;
        }
    }
}

// ---------------------------------------------------------------------------
// Kernel 2: deterministic split-K reduction -> g_A, g_B  ([k, d])
// ---------------------------------------------------------------------------
__global__ void reduce_partials(int kd)
{
    int idx = blockIdx.x * blockDim.x + threadIdx.x;
    if (idx >= 2 * kd) return;
    int z = idx / kd;
    int e = idx - z * kd;
    const float* P = g_partial + (size_t)z * NSPLIT * kd;
    float sum = 0.f;
    #pragma unroll 4
    for (int s = 0; s < NSPLIT; s++) sum += P[(size_t)s * kd + e];
    (z ? g_B : g_A)[e] = sum;
}

// ---------------------------------------------------------------------------
// Kernel 3: Gram matrices. AAt[i,j] = A_i . A_j ;  BAt[i,j] = B_i . A_j
// ---------------------------------------------------------------------------
__global__ __launch_bounds__(KDIM)
void gram_kernel(int k, int d)
{
    __shared__ float row[DDIM];
    const int i = blockIdx.x;
    const int z = blockIdx.y;
    const int j = threadIdx.x;
    const float* src = z ? g_B : g_A;
    for (int t = j; t < d; t += KDIM) row[t] = src[i * d + t];
    __syncthreads();
    const float* aj = g_A + j * d;
    float sum = 0.f;
    #pragma unroll 8
    for (int t = 0; t < d; t++) sum = fmaf(row[t], aj[t], sum);
    (z ? g_BAt : g_AAt)[i * k + j] = sum;
}

// ---------------------------------------------------------------------------
// Kernel 4: one CTA per output row i. Blocked Cholesky (NB=16) + fwd/bwd subs.
// rsqrt + reciprocal table keep IEEE slow paths out of the serial chains.
// ---------------------------------------------------------------------------
__global__ __launch_bounds__(512, 1)
void solve_kernel(const float* __restrict__ evx, const float* __restrict__ evy,
                  float* __restrict__ out)
{
    __shared__ float P[KDIM * (KDIM + 1) / 2];
    __shared__ float colb[NB][KDIM];
    __shared__ float yv[KDIM];
    __shared__ float invD[KDIM];

    const int i   = blockIdx.x;
    const int tid = threadIdx.x;
    const int t   = tid & 127;
    const int q   = tid >> 7;
    const int trit = t * (t + 1) / 2;

    for (int r0 = 0; r0 < KDIM; r0 += 4) {
        int r = r0 + q;
        if (t <= r) P[r * (r + 1) / 2 + t] = g_AAt[r * KDIM + t];
    }
    if (tid < KDIM) yv[tid] = g_BAt[i * KDIM + tid];
    __syncthreads();

    if (tid < KDIM) {
        float ev = evx[tid] - evy[i];
        P[trit + tid] += LAMBDA * ev * ev;
    }
    __syncthreads();

    // ================= blocked Cholesky =================
    for (int b = 0; b < KDIM / NB; b++) {
        const int j0  = b * NB;
        const int rlo = j0 + NB;

        if (tid < 32) {
            int lrow = tid & 15;
            int row = j0 + lrow;
            int trow = row * (row + 1) / 2;
            float dreg[NB];
            float myinv = 0.f;
            #pragma unroll
            for (int c = 0; c < NB; c++)
                dreg[c] = (c <= lrow) ? P[trow + j0 + c] : 0.f;

            #pragma unroll
            for (int c = 0; c < NB; c++) {
                float dc = __shfl_sync(0xffffffffu, dreg[c], c);
                float r  = rsqrtf(dc);
                if (lrow == c)      { dreg[c] = dc * r; myinv = r; }
                else if (lrow > c)  dreg[c] *= r;
                #pragma unroll
                for (int m = c + 1; m < NB; m++) {
                    float Lmc = __shfl_sync(0xffffffffu, dreg[c], m);
                    if (lrow >= m) dreg[m] -= dreg[c] * Lmc;
                }
            }
            if (tid < 16) {
                #pragma unroll
                for (int c = 0; c < NB; c++)
                    if (c <= lrow) P[trow + j0 + c] = dreg[c];
                invD[row] = myinv;
            }
        }
        __syncthreads();

        if (rlo >= KDIM) break;

        {
            int r = rlo + tid;
            if (r < KDIM) {
                int trr = r * (r + 1) / 2;
                float a[NB];
                #pragma unroll
                for (int j = 0; j < NB; j++) a[j] = P[trr + j0 + j];
                #pragma unroll
                for (int j = 0; j < NB; j++) {
                    float v = a[j];
                    int trj = (j0 + j) * (j0 + j + 1) / 2;
                    #pragma unroll
                    for (int c = 0; c < j; c++)
                        v -= a[c] * P[trj + j0 + c];
                    a[j] = v * invD[j0 + j];
                }
                #pragma unroll
                for (int j = 0; j < NB; j++) {
                    P[trr + j0 + j] = a[j];
                    colb[j][r] = a[j];
                }
            }
        }
        __syncthreads();

        if (t >= rlo) {
            float ar[NB];
            #pragma unroll
            for (int j = 0; j < NB; j++) ar[j] = colb[j][t];
            for (int c = rlo + q; c <= t; c += 4) {
                float a2 = P[trit + c];
                #pragma unroll
                for (int j = 0; j < NB; j++) a2 -= ar[j] * colb[j][c];
                P[trit + c] = a2;
            }
        }
        __syncthreads();
    }

    // ================= forward substitution =================
    for (int b = 0; b < KDIM / NB; b++) {
        const int j0 = b * NB;
        if (tid < 32) {
            int lrow = tid & 15;
            int row = j0 + lrow;
            int trow = row * (row + 1) / 2;
            float yl = yv[row];
            #pragma unroll
            for (int c = 0; c < NB; c++) {
                int rc = j0 + c;
                float t2 = yl * invD[rc];
                yl = (lrow == c) ? t2 : yl;
                float yc = __shfl_sync(0xffffffffu, yl, c);
                if (lrow > c) yl -= P[trow + rc] * yc;
            }
            if (tid < 16) yv[row] = yl;
        }
        __syncthreads();
        {
            int r = j0 + NB + tid;
            if (r < KDIM) {
                int trr = r * (r + 1) / 2;
                float a2 = yv[r];
                #pragma unroll
                for (int c = 0; c < NB; c++)
                    a2 -= P[trr + j0 + c] * yv[j0 + c];
                yv[r] = a2;
            }
        }
        __syncthreads();
    }

    // ================= backward substitution =================
    for (int b = KDIM / NB - 1; b >= 0; b--) {
        const int j0 = b * NB;
        if (tid < 32) {
            int lrow = tid & 15;
            int row = j0 + lrow;
            float xl = yv[row];
            #pragma unroll
            for (int c = NB - 1; c >= 0; c--) {
                int rc = j0 + c;
                int trc = rc * (rc + 1) / 2;
                float t2 = xl * invD[rc];
                xl = (lrow == c) ? t2 : xl;
                float xc = __shfl_sync(0xffffffffu, xl, c);
                if (lrow < c) xl -= P[trc + row] * xc;
            }
            if (tid < 16) yv[row] = xl;
        }
        __syncthreads();
        {
            int r = tid;
            if (r < j0) {
                float a2 = yv[r];
                #pragma unroll
                for (int c = 0; c < NB; c++) {
                    int rc = j0 + c;
                    a2 -= P[rc * (rc + 1) / 2 + r] * yv[rc];
                }
                yv[r] = a2;
            }
        }
        __syncthreads();
    }

    if (tid < KDIM) out[i * KDIM + tid] = yv[tid];
}

// ---------------------------------------------------------------------------
// Launch
// ---------------------------------------------------------------------------
extern "C" void kernel_launch(void* const* d_in, const int* in_sizes, int n_in,
                              void* d_out, int out_size)
{
    const float* feat_x = (const float*)d_in[0];
    const float* feat_y = (const float*)d_in[1];
    const float* evals_x = (const float*)d_in[2];
    const float* evals_y = (const float*)d_in[3];
    const float* Ex = (const float*)d_in[4];
    const float* Ey = (const float*)d_in[5];

    const int  k  = in_sizes[2];                  // 128
    const long N  = (long)in_sizes[4] / k;        // 200000
    const int  d  = (int)((long)in_sizes[0] / N); // 256
    const int  kd = k * d;

    int Kc = (int)((N + NSPLIT - 1) / NSPLIT);
    Kc = ((Kc + KB - 1) / KB) * KB;

    cudaFuncSetAttribute(gemm_mma, cudaFuncAttributeMaxDynamicSharedMemorySize, SMEM_GEMM);

    dim3 ggrid(2, NSPLIT, 2);
    gemm_mma<<<ggrid, 256, SMEM_GEMM>>>(Ex, feat_x, Ey, feat_y, (int)N, d, Kc, kd);

    reduce_partials<<<(2 * kd + 255) / 256, 256>>>(kd);

    gram_kernel<<<dim3(k, 2), KDIM>>>(k, d);

    solve_kernel<<<k, 512>>>(evals_x, evals_y, (float*)d_out);
}